// round 12
// baseline (speedup 1.0000x reference)
#include <cuda_runtime.h>
#include <cuda_bf16.h>
#include <math.h>
#include <stdint.h>

// ===========================================================================
// SelfAttentionV3 via mma.sync (HMMA) bf16x3 split GEMMs. sm_103 base target.
// R12: term-major MMA issue order — break the 3-deep accumulator RAW chains
// (R11 issued hi*hi, hi*lo, lo*hi back-to-back into the same acc; with the
// barrier phase-locking all warps, the tensor pipe drained on latency).
// ===========================================================================

#define SA_STRIDE 64                 // bytes per SMEM row (XOR swizzle, no pad)
#define TILE_SM   (128 * SA_STRIDE)  // 8192 B, one 128x32 bf16 tile
#define STAGE_SM  (4 * TILE_SM)      // Ahi, Alo, Bhi, Blo = 32768 B
#define NSTAGE    3
#define GEMM_SMEM (NSTAGE * STAGE_SM)  // 98304 B

// swizzled byte offset of 16B chunk c0 (0..3) in row r
#define SWZ(r, c0) (((r) << 6) + ((((c0) ^ (((r) >> 1) & 3))) << 4))

// ------------------------------- scratch ----------------------------------
__device__ __nv_bfloat16 g_xh[8192LL * 1024], g_xl[8192LL * 1024];
__device__ __nv_bfloat16 g_pwh[3072LL * 1024], g_pwl[3072LL * 1024];
__device__ __nv_bfloat16 g_owh[1024LL * 1024], g_owl[1024LL * 1024];
__device__ float         g_qkv[8192LL * 3072];
__device__ __nv_bfloat16 g_qkh[8192LL * 3072], g_qkl[8192LL * 3072];
__device__ __nv_bfloat16 g_vth[4LL * 1024 * 2048], g_vtl[4LL * 1024 * 2048];
__device__ float         g_scores[4LL * 2048 * 2048];
__device__ __nv_bfloat16 g_ah[4LL * 2048 * 2048], g_al[4LL * 2048 * 2048];
__device__ float         g_ctx[8192LL * 1024];
__device__ __nv_bfloat16 g_ch[8192LL * 1024], g_cl[8192LL * 1024];

// ------------------------------- helpers ----------------------------------
__device__ __forceinline__ uint32_t smem_u32(const void* p) {
    uint32_t a;
    asm("{ .reg .u64 t; cvta.to.shared.u64 t, %1; cvt.u32.u64 %0, t; }"
        : "=r"(a) : "l"(p));
    return a;
}

__device__ __forceinline__ void ldsm4(uint32_t* r, uint32_t addr) {
    asm volatile("ldmatrix.sync.aligned.m8n8.x4.shared.b16 {%0,%1,%2,%3}, [%4];"
                 : "=r"(r[0]), "=r"(r[1]), "=r"(r[2]), "=r"(r[3]) : "r"(addr));
}
__device__ __forceinline__ void mma16816(float* d, const uint32_t* a,
                                         const uint32_t* b) {
    asm volatile(
        "mma.sync.aligned.m16n8k16.row.col.f32.bf16.bf16.f32 "
        "{%0,%1,%2,%3},{%4,%5,%6,%7},{%8,%9},{%0,%1,%2,%3};"
        : "+f"(d[0]), "+f"(d[1]), "+f"(d[2]), "+f"(d[3])
        : "r"(a[0]), "r"(a[1]), "r"(a[2]), "r"(a[3]), "r"(b[0]), "r"(b[1]));
}
__device__ __forceinline__ void cp16(uint32_t dst, const void* src) {
    asm volatile("cp.async.cg.shared.global [%0], [%1], 16;"
                 :: "r"(dst), "l"(src) : "memory");
}
#define CP_COMMIT() asm volatile("cp.async.commit_group;" ::: "memory")
#define CP_WAIT(N)  asm volatile("cp.async.wait_group %0;" :: "n"(N) : "memory")

// ---------------------------------------------------------------------------
// HMMA bf16x3 GEMM: C = alpha*(Ah+Al)[M,K]*(Bh+Bl)[N,K]^T (+bias) (+hi/lo out)
// CTA 128x128, 256 thr, warp tile 64x32, BK=32, 3-stage cp.async pipeline.
// __launch_bounds__(256, 2): 128-reg clamp so 2 CTAs/SM fit the 64K RF.
// ---------------------------------------------------------------------------
template <bool HASBIAS, bool WRITE_HILO>
__global__ __launch_bounds__(256, 2) void gemm_hmma3(
    const __nv_bfloat16* __restrict__ Ah, const __nv_bfloat16* __restrict__ Al,
    int lda, long long strideA,
    const __nv_bfloat16* __restrict__ Bh, const __nv_bfloat16* __restrict__ Bl,
    int ldb, long long strideB,
    float* __restrict__ C, int ldc, long long strideC,
    __nv_bfloat16* __restrict__ Ch, __nv_bfloat16* __restrict__ Cl,
    int K, float alpha, const float* __restrict__ bias)
{
    extern __shared__ char smem[];
    const uint32_t sb = smem_u32(smem);

    const int tid  = threadIdx.x;
    const int lane = tid & 31;
    const int wid  = tid >> 5;
    const int wm0  = (wid & 1) * 64;   // warp row offset
    const int wn0  = (wid >> 1) * 32;  // warp col offset

    Ah += blockIdx.z * strideA;  Al += blockIdx.z * strideA;
    Bh += blockIdx.z * strideB;  Bl += blockIdx.z * strideB;
    const long long bm = blockIdx.y * 128LL, bn = blockIdx.x * 128LL;

    // ---- loader: each thread owns 2 contiguous 16B chunks per tile ----
    const int lrow = tid >> 1;
    const int c0b  = (tid & 1) * 2;        // first chunk index (0 or 2)
    const char* gAh = (const char*)(Ah + (bm + lrow) * (long long)lda) + c0b * 16;
    const char* gAl = (const char*)(Al + (bm + lrow) * (long long)lda) + c0b * 16;
    const char* gBh = (const char*)(Bh + (bn + lrow) * (long long)ldb) + c0b * 16;
    const char* gBl = (const char*)(Bl + (bn + lrow) * (long long)ldb) + c0b * 16;
    const uint32_t sw0 = SWZ(lrow, c0b + 0);
    const uint32_t sw1 = SWZ(lrow, c0b + 1);

    // ---- ldmatrix per-lane components (non-trans, K-major both operands) ----
    const uint32_t aRow = lane & 15;
    const uint32_t aCh  = lane >> 4;                         // chunk 0/1 base
    const uint32_t bN   = (lane & 7) | ((lane & 16) >> 1);
    const uint32_t bCh  = (lane >> 3) & 1;

    uint32_t aBase[4], aSw[4], bBase[2], bSw[2];
#pragma unroll
    for (int mg = 0; mg < 4; mg++) {
        const uint32_t r = wm0 + mg * 16 + aRow;
        aBase[mg] = r << 6;  aSw[mg] = (r >> 1) & 3;
    }
#pragma unroll
    for (int p = 0; p < 2; p++) {
        const uint32_t r = wn0 + p * 16 + bN;
        bBase[p] = r << 6;  bSw[p] = (r >> 1) & 3;
    }

    float acc[4][4][4];
#pragma unroll
    for (int i = 0; i < 4; i++)
#pragma unroll
        for (int j = 0; j < 4; j++)
#pragma unroll
            for (int r = 0; r < 4; r++) acc[i][j][r] = 0.0f;

    const int nst = K >> 5;

    // ---- prologue: issue stages 0 and 1 ----
#pragma unroll
    for (int s = 0; s < 2; s++) {
        if (s < nst) {
            const uint32_t st = sb + s * STAGE_SM;
            const long long kb = (long long)s * 64;
            cp16(st + 0 * TILE_SM + sw0, gAh + kb);  cp16(st + 0 * TILE_SM + sw1, gAh + kb + 16);
            cp16(st + 1 * TILE_SM + sw0, gAl + kb);  cp16(st + 1 * TILE_SM + sw1, gAl + kb + 16);
            cp16(st + 2 * TILE_SM + sw0, gBh + kb);  cp16(st + 2 * TILE_SM + sw1, gBh + kb + 16);
            cp16(st + 3 * TILE_SM + sw0, gBl + kb);  cp16(st + 3 * TILE_SM + sw1, gBl + kb + 16);
            CP_COMMIT();
        }
    }

    int stage = 0;
    for (int i = 0; i < nst; i++) {
        if (i + 1 < nst) { CP_WAIT(1); } else { CP_WAIT(0); }  // stage i arrived
        __syncthreads();  // all warps done reading buffer refilled below

        if (i + 2 < nst) {
            const uint32_t st = sb + ((stage + 2) % NSTAGE) * STAGE_SM;
            const long long kb = (long long)(i + 2) * 64;
            cp16(st + 0 * TILE_SM + sw0, gAh + kb);  cp16(st + 0 * TILE_SM + sw1, gAh + kb + 16);
            cp16(st + 1 * TILE_SM + sw0, gAl + kb);  cp16(st + 1 * TILE_SM + sw1, gAl + kb + 16);
            cp16(st + 2 * TILE_SM + sw0, gBh + kb);  cp16(st + 2 * TILE_SM + sw1, gBh + kb + 16);
            cp16(st + 3 * TILE_SM + sw0, gBl + kb);  cp16(st + 3 * TILE_SM + sw1, gBl + kb + 16);
            CP_COMMIT();
        }

        const uint32_t st = sb + stage * STAGE_SM;
#pragma unroll
        for (int ks = 0; ks < 2; ks++) {
            const uint32_t kc = ks * 2;  // chunk offset for this k-half
            uint32_t ahi[4][4], alo[4][4], bhi[4][2], blo[4][2];
#pragma unroll
            for (int mg = 0; mg < 4; mg++) {
                const uint32_t ro = aBase[mg] + (((aCh + kc) ^ aSw[mg]) << 4);
                ldsm4(ahi[mg], st + 0 * TILE_SM + ro);
                ldsm4(alo[mg], st + 1 * TILE_SM + ro);
            }
#pragma unroll
            for (int p = 0; p < 2; p++) {
                const uint32_t ro = bBase[p] + (((bCh + kc) ^ bSw[p]) << 4);
                uint32_t t[4];
                ldsm4(t, st + 2 * TILE_SM + ro);
                bhi[2 * p][0] = t[0]; bhi[2 * p][1] = t[1];
                bhi[2 * p + 1][0] = t[2]; bhi[2 * p + 1][1] = t[3];
                ldsm4(t, st + 3 * TILE_SM + ro);
                blo[2 * p][0] = t[0]; blo[2 * p][1] = t[1];
                blo[2 * p + 1][0] = t[2]; blo[2 * p + 1][1] = t[3];
            }
            // term-major issue: same-acc MMAs separated by 16 independent ones.
            // fp32 accumulation order per acc unchanged (hi*hi, hi*lo, lo*hi).
#pragma unroll
            for (int mg = 0; mg < 4; mg++)
#pragma unroll
                for (int ng = 0; ng < 4; ng++)
                    mma16816(acc[mg][ng], ahi[mg], bhi[ng]);
#pragma unroll
            for (int mg = 0; mg < 4; mg++)
#pragma unroll
                for (int ng = 0; ng < 4; ng++)
                    mma16816(acc[mg][ng], ahi[mg], blo[ng]);
#pragma unroll
            for (int mg = 0; mg < 4; mg++)
#pragma unroll
                for (int ng = 0; ng < 4; ng++)
                    mma16816(acc[mg][ng], alo[mg], bhi[ng]);
        }
        stage = (stage + 1 == NSTAGE) ? 0 : stage + 1;
    }

    // ---- epilogue ----
    C += blockIdx.z * strideC;
    if (WRITE_HILO) { Ch += blockIdx.z * strideC; Cl += blockIdx.z * strideC; }

#pragma unroll
    for (int mg = 0; mg < 4; mg++) {
#pragma unroll
        for (int ng = 0; ng < 4; ng++) {
            const long long r0 = bm + wm0 + mg * 16 + (lane >> 2);
            const long long c0 = bn + wn0 + ng * 8 + (lane & 3) * 2;
#pragma unroll
            for (int h = 0; h < 2; h++) {
                float2 v;
                v.x = acc[mg][ng][2 * h + 0] * alpha;
                v.y = acc[mg][ng][2 * h + 1] * alpha;
                if (HASBIAS) { v.x += bias[c0]; v.y += bias[c0 + 1]; }
                const long long off = (r0 + 8 * h) * ldc + c0;
                *(float2*)(C + off) = v;
                if (WRITE_HILO) {
                    __nv_bfloat16 hx = __float2bfloat16(v.x);
                    __nv_bfloat16 hy = __float2bfloat16(v.y);
                    __nv_bfloat16 lx = __float2bfloat16(v.x - __bfloat162float(hx));
                    __nv_bfloat16 ly = __float2bfloat16(v.y - __bfloat162float(hy));
                    *(__nv_bfloat162*)(Ch + off) = __halves2bfloat162(hx, hy);
                    *(__nv_bfloat162*)(Cl + off) = __halves2bfloat162(lx, ly);
                }
            }
        }
    }
}

// ---------------------------------------------------------------------------
// fp32 -> (bf16 hi, bf16 lo), 4 elems/thread
// ---------------------------------------------------------------------------
__global__ __launch_bounds__(256) void convert_hilo(
    const float4* __restrict__ in, __nv_bfloat16* __restrict__ h,
    __nv_bfloat16* __restrict__ l, long long n4)
{
    long long i = blockIdx.x * 256LL + threadIdx.x;
    if (i >= n4) return;
    float4 v = in[i];
    float f[4] = {v.x, v.y, v.z, v.w};
    __nv_bfloat16 hh[4], ll[4];
#pragma unroll
    for (int j = 0; j < 4; j++) {
        hh[j] = __float2bfloat16(f[j]);
        ll[j] = __float2bfloat16(f[j] - __bfloat162float(hh[j]));
    }
    __nv_bfloat162* hp = (__nv_bfloat162*)(h + i * 4);
    __nv_bfloat162* lp = (__nv_bfloat162*)(l + i * 4);
    hp[0] = __halves2bfloat162(hh[0], hh[1]);
    hp[1] = __halves2bfloat162(hh[2], hh[3]);
    lp[0] = __halves2bfloat162(ll[0], ll[1]);
    lp[1] = __halves2bfloat162(ll[2], ll[3]);
}

// ---------------------------------------------------------------------------
// fp32 [R,C] -> bf16 hi/lo [C,R], batched
// ---------------------------------------------------------------------------
__global__ __launch_bounds__(256) void transpose_hilo(
    const float* __restrict__ in, long long inStride, int ldin,
    __nv_bfloat16* __restrict__ oh, __nv_bfloat16* __restrict__ ol,
    long long outStride, int ldout)
{
    __shared__ float t[32][33];
    in += blockIdx.z * inStride;
    oh += blockIdx.z * outStride;
    ol += blockIdx.z * outStride;
    const int r0 = blockIdx.y * 32, c0 = blockIdx.x * 32;
    const int tx = threadIdx.x, ty = threadIdx.y;
#pragma unroll
    for (int j = ty; j < 32; j += 8)
        t[j][tx] = in[(long long)(r0 + j) * ldin + c0 + tx];
    __syncthreads();
#pragma unroll
    for (int j = ty; j < 32; j += 8) {
        float v = t[tx][j];
        __nv_bfloat16 h = __float2bfloat16(v);
        __nv_bfloat16 l = __float2bfloat16(v - __bfloat162float(h));
        long long o = (long long)(c0 + j) * ldout + r0 + tx;
        oh[o] = h; ol[o] = l;
    }
}

// ---------------------------------------------------------------------------
// masked softmax over rows of 2048, emits attn as bf16 hi/lo
// ---------------------------------------------------------------------------
__global__ __launch_bounds__(256) void softmax_mask_kernel(
    const float* __restrict__ scores, const int* __restrict__ mask,
    __nv_bfloat16* __restrict__ ah, __nv_bfloat16* __restrict__ al)
{
    const long long base = ((long long)blockIdx.y * 2048 + blockIdx.x) * 2048;
    const float* srow = scores + base;
    const int* mrow = mask + base;
    const int tid = threadIdx.x;

    float vals[8];
    float lmax = -INFINITY;
#pragma unroll
    for (int i = 0; i < 8; i++) {
        const int idx = tid + i * 256;
        float s = srow[idx];
        if (mrow[idx] == 0) s = -1e20f;
        vals[i] = s;
        lmax = fmaxf(lmax, s);
    }
    __shared__ float red[256];
    red[tid] = lmax;
    __syncthreads();
#pragma unroll
    for (int off = 128; off >= 1; off >>= 1) {
        if (tid < off) red[tid] = fmaxf(red[tid], red[tid + off]);
        __syncthreads();
    }
    const float m = red[0];
    __syncthreads();
    float lsum = 0.0f;
#pragma unroll
    for (int i = 0; i < 8; i++) { vals[i] = __expf(vals[i] - m); lsum += vals[i]; }
    red[tid] = lsum;
    __syncthreads();
#pragma unroll
    for (int off = 128; off >= 1; off >>= 1) {
        if (tid < off) red[tid] += red[tid + off];
        __syncthreads();
    }
    const float inv = 1.0f / red[0];
#pragma unroll
    for (int i = 0; i < 8; i++) {
        const int idx = tid + i * 256;
        float p = vals[i] * inv;
        __nv_bfloat16 h = __float2bfloat16(p);
        ah[base + idx] = h;
        al[base + idx] = __float2bfloat16(p - __bfloat162float(h));
    }
}

// ---------------------------------------------------------------------------
// kernel_launch. inputs: x, attention_mask, proj_w, proj_b, out_w, out_b
// ---------------------------------------------------------------------------
extern "C" void kernel_launch(void* const* d_in, const int* in_sizes, int n_in,
                              void* d_out, int out_size)
{
    const float* x      = (const float*)d_in[0];
    const int*   mask   = (const int*)  d_in[1];
    const float* proj_w = (const float*)d_in[2];
    const float* proj_b = (const float*)d_in[3];
    const float* out_w  = (const float*)d_in[4];
    const float* out_b  = (const float*)d_in[5];
    float*       out    = (float*)d_out;

    __nv_bfloat16 *xh, *xl, *pwh, *pwl, *owh, *owl, *qkh, *qkl, *vth, *vtl,
                  *ah, *al, *ch, *cl;
    float *qkv, *scores, *ctx;
    cudaGetSymbolAddress((void**)&xh, g_xh);   cudaGetSymbolAddress((void**)&xl, g_xl);
    cudaGetSymbolAddress((void**)&pwh, g_pwh); cudaGetSymbolAddress((void**)&pwl, g_pwl);
    cudaGetSymbolAddress((void**)&owh, g_owh); cudaGetSymbolAddress((void**)&owl, g_owl);
    cudaGetSymbolAddress((void**)&qkv, g_qkv);
    cudaGetSymbolAddress((void**)&qkh, g_qkh); cudaGetSymbolAddress((void**)&qkl, g_qkl);
    cudaGetSymbolAddress((void**)&vth, g_vth); cudaGetSymbolAddress((void**)&vtl, g_vtl);
    cudaGetSymbolAddress((void**)&scores, g_scores);
    cudaGetSymbolAddress((void**)&ah, g_ah);   cudaGetSymbolAddress((void**)&al, g_al);
    cudaGetSymbolAddress((void**)&ctx, g_ctx);
    cudaGetSymbolAddress((void**)&ch, g_ch);   cudaGetSymbolAddress((void**)&cl, g_cl);

    cudaFuncSetAttribute(gemm_hmma3<true, true>,
                         cudaFuncAttributeMaxDynamicSharedMemorySize, GEMM_SMEM);
    cudaFuncSetAttribute(gemm_hmma3<true, false>,
                         cudaFuncAttributeMaxDynamicSharedMemorySize, GEMM_SMEM);
    cudaFuncSetAttribute(gemm_hmma3<false, false>,
                         cudaFuncAttributeMaxDynamicSharedMemorySize, GEMM_SMEM);
    cudaFuncSetAttribute(gemm_hmma3<false, true>,
                         cudaFuncAttributeMaxDynamicSharedMemorySize, GEMM_SMEM);

    const long long qkvStride = 2048LL * 3072;
    const long long scStride  = 2048LL * 2048;
    const long long ctxStride = 2048LL * 1024;
    const long long vtStride  = 1024LL * 2048;

    // 0) operand prep
    convert_hilo<<<(8192LL * 1024 / 4 + 255) / 256, 256>>>(
        (const float4*)x, xh, xl, 8192LL * 1024 / 4);
    transpose_hilo<<<dim3(3072 / 32, 1024 / 32, 1), dim3(32, 8)>>>(
        proj_w, 0, 3072, pwh, pwl, 0, 1024);
    transpose_hilo<<<dim3(1024 / 32, 1024 / 32, 1), dim3(32, 8)>>>(
        out_w, 0, 1024, owh, owl, 0, 1024);

    // 1) qkv = x @ proj_w + proj_b   [8192,1024]x[3072,1024]^T, hi/lo fused out
    gemm_hmma3<true, true><<<dim3(24, 64, 1), 256, GEMM_SMEM>>>(
        xh, xl, 1024, 0, pwh, pwl, 1024, 0,
        qkv, 3072, 0, qkh, qkl, 1024, 1.0f, proj_b);

    // v^T per batch: [2048,1024] -> [1024,2048] hi/lo
    transpose_hilo<<<dim3(1024 / 32, 2048 / 32, 4), dim3(32, 8)>>>(
        qkv + 2048, qkvStride, 3072, vth, vtl, vtStride, 2048);

    // 2) scores = (q @ k^T) / 32, batched
    gemm_hmma3<false, false><<<dim3(16, 16, 4), 256, GEMM_SMEM>>>(
        qkh, qkl, 3072, qkvStride, qkh + 1024, qkl + 1024, 3072, qkvStride,
        scores, 2048, scStride, nullptr, nullptr, 1024, 0.03125f, nullptr);

    // 3) masked softmax -> attn hi/lo
    softmax_mask_kernel<<<dim3(2048, 4, 1), 256>>>(scores, mask, ah, al);

    // 4) ctx = attn @ v, batched; hi/lo fused out
    gemm_hmma3<false, true><<<dim3(8, 16, 4), 256, GEMM_SMEM>>>(
        ah, al, 2048, scStride, vth, vtl, 2048, vtStride,
        ctx, 1024, ctxStride, ch, cl, 2048, 1.0f, nullptr);

    // 5) out = ctx @ out_w + out_b
    gemm_hmma3<true, false><<<dim3(8, 64, 1), 256, GEMM_SMEM>>>(
        ch, cl, 1024, 0, owh, owl, 1024, 0,
        out, 1024, 0, nullptr, nullptr, 1024, 1.0f, out_b);
}

// round 17
// speedup vs baseline: 1.2450x; 1.2450x over previous
#include <cuda_runtime.h>
#include <cuda_bf16.h>
#include <math.h>
#include <stdint.h>

// ===========================================================================
// SelfAttentionV3 via mma.sync m16n8k8 TF32, single pass. sm_103 base target.
// R14 = R13 resubmit (infra failure) + cvt.rna.tf32 asm constraint hardening
// ("=r" b32 dest instead of "=f"; some ptxas reject float regs for tf32 cvt).
// All operands RTN-rounded to tf32 BEFORE the GEMM; products exact in fp32.
//   qkv = x @ proj_w + b ; scores = qk^T/32 ; mask+softmax ; ctx = attn @ v
//   out = ctx @ out_w + b     All GEMMs: D = A[M,K] * B[N,K]^T, fp32 K-major.
// ===========================================================================

#define TILE_SM   16384              // 128 rows x 128 B (32 fp32), swizzled
#define STAGE_SM  (2 * TILE_SM)      // A, B = 32768 B
#define NSTAGE    3
#define GEMM_SMEM (NSTAGE * STAGE_SM)  // 98304 B

// ------------------------------- scratch ----------------------------------
__device__ float g_xt[8192LL * 1024];        // x, tf32-rounded
__device__ float g_pwt[3072LL * 1024];       // proj_w^T, rounded
__device__ float g_owt[1024LL * 1024];       // out_w^T, rounded
__device__ float g_qkv[8192LL * 3072];       // qkv, rounded at epilogue
__device__ float g_vt[4LL * 1024 * 2048];    // v^T per batch, rounded
__device__ float g_scores[4LL * 2048 * 2048];// scores -> attn in place
__device__ float g_ctx[8192LL * 1024];       // ctx, rounded

// ------------------------------- helpers ----------------------------------
__device__ __forceinline__ uint32_t smem_u32(const void* p) {
    uint32_t a;
    asm("{ .reg .u64 t; cvta.to.shared.u64 t, %1; cvt.u32.u64 %0, t; }"
        : "=r"(a) : "l"(p));
    return a;
}
__device__ __forceinline__ float rna_tf32(float x) {
    uint32_t y;
    asm("cvt.rna.tf32.f32 %0, %1;" : "=r"(y) : "f"(x));
    return __uint_as_float(y);
}
__device__ __forceinline__ void ldsm4(uint32_t* r, uint32_t addr) {
    asm volatile("ldmatrix.sync.aligned.m8n8.x4.shared.b16 {%0,%1,%2,%3}, [%4];"
                 : "=r"(r[0]), "=r"(r[1]), "=r"(r[2]), "=r"(r[3]) : "r"(addr));
}
__device__ __forceinline__ void mma_tf32(float* d, const uint32_t* a,
                                         const uint32_t* b) {
    asm volatile(
        "mma.sync.aligned.m16n8k8.row.col.f32.tf32.tf32.f32 "
        "{%0,%1,%2,%3},{%4,%5,%6,%7},{%8,%9},{%0,%1,%2,%3};"
        : "+f"(d[0]), "+f"(d[1]), "+f"(d[2]), "+f"(d[3])
        : "r"(a[0]), "r"(a[1]), "r"(a[2]), "r"(a[3]), "r"(b[0]), "r"(b[1]));
}
__device__ __forceinline__ void cp16(uint32_t dst, const void* src) {
    asm volatile("cp.async.cg.shared.global [%0], [%1], 16;"
                 :: "r"(dst), "l"(src) : "memory");
}
#define CP_COMMIT() asm volatile("cp.async.commit_group;" ::: "memory")
#define CP_WAIT(N)  asm volatile("cp.async.wait_group %0;" :: "n"(N) : "memory")

// ---------------------------------------------------------------------------
// TF32 GEMM: C = alpha * A[M,K] * B[N,K]^T (+bias), fp32 ops pre-rounded tf32.
// CTA 128x128, 256 thr, 8 warps (2x4), warp tile 64x32, BK=32 fp32,
// 3-stage cp.async pipeline, swizzle chunk' = chunk ^ (row&7) on 128B rows.
// ---------------------------------------------------------------------------
template <bool HASBIAS, bool ROUND_OUT>
__global__ __launch_bounds__(256, 2) void gemm_tf32(
    const float* __restrict__ A, int lda, long long strideA,
    const float* __restrict__ B, int ldb, long long strideB,
    float* __restrict__ C, int ldc, long long strideC,
    int K, float alpha, const float* __restrict__ bias)
{
    extern __shared__ char smem[];
    const uint32_t sb = smem_u32(smem);

    const int tid  = threadIdx.x;
    const int lane = tid & 31;
    const int wid  = tid >> 5;
    const int wm0  = (wid & 1) * 64;   // warp row offset
    const int wn0  = (wid >> 1) * 32;  // warp col offset

    A += blockIdx.z * strideA;
    B += blockIdx.z * strideB;
    const long long bm = blockIdx.y * 128LL, bn = blockIdx.x * 128LL;

    // ---- loader: thread owns row (tid>>1), chunks 4*(tid&1)..+3 ----
    const int lrow = tid >> 1;
    const int half = tid & 1;
    const char* gA = (const char*)(A + (bm + lrow) * (long long)lda) + half * 64;
    const char* gB = (const char*)(B + (bn + lrow) * (long long)ldb) + half * 64;
    uint32_t swd[4];
#pragma unroll
    for (int c = 0; c < 4; c++)
        swd[c] = lrow * 128 + (((half * 4 + c) ^ (lrow & 7)) << 4);

    // ---- ldmatrix lane components ----
    const uint32_t aRow = lane & 15;                        // A row in m16
    const uint32_t aCh  = lane >> 4;                        // chunk half (0/1)
    const uint32_t bN   = (lane & 7) | ((lane & 16) >> 1);  // B n-row in 16
    const uint32_t bCh  = (lane >> 3) & 1;                  // chunk half

    uint32_t aAddr[4], bAddr[2];
    const uint32_t aSw = aRow & 7, bSw = bN & 7;
#pragma unroll
    for (int mg = 0; mg < 4; mg++)
        aAddr[mg] = (wm0 + mg * 16 + aRow) * 128;
#pragma unroll
    for (int p = 0; p < 2; p++)
        bAddr[p] = (wn0 + p * 16 + bN) * 128;

    float acc[4][4][4];
#pragma unroll
    for (int i = 0; i < 4; i++)
#pragma unroll
        for (int j = 0; j < 4; j++)
#pragma unroll
            for (int r = 0; r < 4; r++) acc[i][j][r] = 0.0f;

    const int nst = K >> 5;

    // ---- prologue: stages 0, 1 ----
#pragma unroll
    for (int s = 0; s < 2; s++) {
        if (s < nst) {
            const uint32_t st = sb + s * STAGE_SM;
#pragma unroll
            for (int c = 0; c < 4; c++) {
                cp16(st + swd[c], gA + s * 128 + c * 16);
                cp16(st + TILE_SM + swd[c], gB + s * 128 + c * 16);
            }
            CP_COMMIT();
        }
    }

    int stage = 0;
    for (int i = 0; i < nst; i++) {
        if (i + 1 < nst) { CP_WAIT(1); } else { CP_WAIT(0); }
        __syncthreads();

        if (i + 2 < nst) {
            const uint32_t st = sb + ((stage + 2) % NSTAGE) * STAGE_SM;
            const long long kb = (long long)(i + 2) * 128;
#pragma unroll
            for (int c = 0; c < 4; c++) {
                cp16(st + swd[c], gA + kb + c * 16);
                cp16(st + TILE_SM + swd[c], gB + kb + c * 16);
            }
            CP_COMMIT();
        }

        const uint32_t st = sb + stage * STAGE_SM;
#pragma unroll
        for (int j = 0; j < 4; j++) {  // four k8 steps
            uint32_t af[4][4], bf[4][2];
#pragma unroll
            for (int mg = 0; mg < 4; mg++)
                ldsm4(af[mg], st + aAddr[mg] + (((2 * j + aCh) ^ aSw) << 4));
#pragma unroll
            for (int p = 0; p < 2; p++) {
                uint32_t t[4];
                ldsm4(t, st + TILE_SM + bAddr[p] + (((2 * j + bCh) ^ bSw) << 4));
                bf[2 * p][0] = t[0];     bf[2 * p][1] = t[1];
                bf[2 * p + 1][0] = t[2]; bf[2 * p + 1][1] = t[3];
            }
#pragma unroll
            for (int mg = 0; mg < 4; mg++)
#pragma unroll
                for (int ng = 0; ng < 4; ng++)
                    mma_tf32(acc[mg][ng], af[mg], bf[ng]);
        }
        stage = (stage + 1 == NSTAGE) ? 0 : stage + 1;
    }

    // ---- epilogue ----
    C += blockIdx.z * strideC;
#pragma unroll
    for (int mg = 0; mg < 4; mg++) {
#pragma unroll
        for (int ng = 0; ng < 4; ng++) {
            const long long r0 = bm + wm0 + mg * 16 + (lane >> 2);
            const long long c0 = bn + wn0 + ng * 8 + (lane & 3) * 2;
#pragma unroll
            for (int h = 0; h < 2; h++) {
                float2 v;
                v.x = acc[mg][ng][2 * h + 0] * alpha;
                v.y = acc[mg][ng][2 * h + 1] * alpha;
                if (HASBIAS) { v.x += bias[c0]; v.y += bias[c0 + 1]; }
                if (ROUND_OUT) { v.x = rna_tf32(v.x); v.y = rna_tf32(v.y); }
                *(float2*)(C + (r0 + 8 * h) * ldc + c0) = v;
            }
        }
    }
}

// ---------------------------------------------------------------------------
// elementwise tf32 RTN rounding, 4 elems/thread
// ---------------------------------------------------------------------------
__global__ __launch_bounds__(256) void round_tf32_kernel(
    const float4* __restrict__ in, float4* __restrict__ out, long long n4)
{
    long long i = blockIdx.x * 256LL + threadIdx.x;
    if (i >= n4) return;
    float4 v = in[i];
    v.x = rna_tf32(v.x); v.y = rna_tf32(v.y);
    v.z = rna_tf32(v.z); v.w = rna_tf32(v.w);
    out[i] = v;
}

// ---------------------------------------------------------------------------
// fp32 [R,C] -> tf32-rounded fp32 [C,R], batched
// ---------------------------------------------------------------------------
__global__ __launch_bounds__(256) void transpose_rna(
    const float* __restrict__ in, long long inStride, int ldin,
    float* __restrict__ out, long long outStride, int ldout)
{
    __shared__ float t[32][33];
    in  += blockIdx.z * inStride;
    out += blockIdx.z * outStride;
    const int r0 = blockIdx.y * 32, c0 = blockIdx.x * 32;
    const int tx = threadIdx.x, ty = threadIdx.y;
#pragma unroll
    for (int j = ty; j < 32; j += 8)
        t[j][tx] = in[(long long)(r0 + j) * ldin + c0 + tx];
    __syncthreads();
#pragma unroll
    for (int j = ty; j < 32; j += 8)
        out[(long long)(c0 + j) * ldout + r0 + tx] = rna_tf32(t[tx][j]);
}

// ---------------------------------------------------------------------------
// masked softmax over rows of 2048, in place, tf32-rounded output
// ---------------------------------------------------------------------------
__global__ __launch_bounds__(256) void softmax_mask_kernel(
    float* __restrict__ scores, const int* __restrict__ mask)
{
    const long long base = ((long long)blockIdx.y * 2048 + blockIdx.x) * 2048;
    float* srow = scores + base;
    const int* mrow = mask + base;
    const int tid = threadIdx.x;

    float vals[8];
    float lmax = -INFINITY;
#pragma unroll
    for (int i = 0; i < 8; i++) {
        const int idx = tid + i * 256;
        float s = srow[idx];
        if (mrow[idx] == 0) s = -1e20f;
        vals[i] = s;
        lmax = fmaxf(lmax, s);
    }
    __shared__ float red[256];
    red[tid] = lmax;
    __syncthreads();
#pragma unroll
    for (int off = 128; off >= 1; off >>= 1) {
        if (tid < off) red[tid] = fmaxf(red[tid], red[tid + off]);
        __syncthreads();
    }
    const float m = red[0];
    __syncthreads();
    float lsum = 0.0f;
#pragma unroll
    for (int i = 0; i < 8; i++) { vals[i] = __expf(vals[i] - m); lsum += vals[i]; }
    red[tid] = lsum;
    __syncthreads();
#pragma unroll
    for (int off = 128; off >= 1; off >>= 1) {
        if (tid < off) red[tid] += red[tid + off];
        __syncthreads();
    }
    const float inv = 1.0f / red[0];
#pragma unroll
    for (int i = 0; i < 8; i++)
        srow[tid + i * 256] = rna_tf32(vals[i] * inv);
}

// ---------------------------------------------------------------------------
// kernel_launch. inputs: x, attention_mask, proj_w, proj_b, out_w, out_b
// ---------------------------------------------------------------------------
extern "C" void kernel_launch(void* const* d_in, const int* in_sizes, int n_in,
                              void* d_out, int out_size)
{
    const float* x      = (const float*)d_in[0];
    const int*   mask   = (const int*)  d_in[1];
    const float* proj_w = (const float*)d_in[2];
    const float* proj_b = (const float*)d_in[3];
    const float* out_w  = (const float*)d_in[4];
    const float* out_b  = (const float*)d_in[5];
    float*       out    = (float*)d_out;

    float *xt, *pwt, *owt, *qkv, *vt, *scores, *ctx;
    cudaGetSymbolAddress((void**)&xt, g_xt);
    cudaGetSymbolAddress((void**)&pwt, g_pwt);
    cudaGetSymbolAddress((void**)&owt, g_owt);
    cudaGetSymbolAddress((void**)&qkv, g_qkv);
    cudaGetSymbolAddress((void**)&vt, g_vt);
    cudaGetSymbolAddress((void**)&scores, g_scores);
    cudaGetSymbolAddress((void**)&ctx, g_ctx);

    cudaFuncSetAttribute(gemm_tf32<true, true>,
                         cudaFuncAttributeMaxDynamicSharedMemorySize, GEMM_SMEM);
    cudaFuncSetAttribute(gemm_tf32<true, false>,
                         cudaFuncAttributeMaxDynamicSharedMemorySize, GEMM_SMEM);
    cudaFuncSetAttribute(gemm_tf32<false, false>,
                         cudaFuncAttributeMaxDynamicSharedMemorySize, GEMM_SMEM);
    cudaFuncSetAttribute(gemm_tf32<false, true>,
                         cudaFuncAttributeMaxDynamicSharedMemorySize, GEMM_SMEM);

    const long long qkvStride = 2048LL * 3072;
    const long long scStride  = 2048LL * 2048;
    const long long ctxStride = 2048LL * 1024;
    const long long vtStride  = 1024LL * 2048;

    // 0) operand prep (RTN tf32 rounding)
    round_tf32_kernel<<<(8192LL * 1024 / 4 + 255) / 256, 256>>>(
        (const float4*)x, (float4*)xt, 8192LL * 1024 / 4);
    transpose_rna<<<dim3(3072 / 32, 1024 / 32, 1), dim3(32, 8)>>>(
        proj_w, 0, 3072, pwt, 0, 1024);
    transpose_rna<<<dim3(1024 / 32, 1024 / 32, 1), dim3(32, 8)>>>(
        out_w, 0, 1024, owt, 0, 1024);

    // 1) qkv = x @ proj_w + proj_b  [8192,1024]x[3072,1024]^T, rounded out
    gemm_tf32<true, true><<<dim3(24, 64, 1), 256, GEMM_SMEM>>>(
        xt, 1024, 0, pwt, 1024, 0, qkv, 3072, 0, 1024, 1.0f, proj_b);

    // v^T per batch: [2048,1024] -> [1024,2048], rounded
    transpose_rna<<<dim3(1024 / 32, 2048 / 32, 4), dim3(32, 8)>>>(
        qkv + 2048, qkvStride, 3072, vt, vtStride, 2048);

    // 2) scores = (q @ k^T) / 32, batched (fp32 out, no rounding)
    gemm_tf32<false, false><<<dim3(16, 16, 4), 256, GEMM_SMEM>>>(
        qkv, 3072, qkvStride, qkv + 1024, 3072, qkvStride,
        scores, 2048, scStride, 1024, 0.03125f, nullptr);

    // 3) masked softmax in place -> attn (tf32-rounded)
    softmax_mask_kernel<<<dim3(2048, 4, 1), 256>>>(scores, mask);

    // 4) ctx = attn @ v, batched, rounded out
    gemm_tf32<false, true><<<dim3(8, 16, 4), 256, GEMM_SMEM>>>(
        scores, 2048, scStride, vt, 2048, vtStride,
        ctx, 1024, ctxStride, 2048, 1.0f, nullptr);

    // 5) out = ctx @ out_w + out_b (full fp32 out)
    gemm_tf32<true, false><<<dim3(8, 64, 1), 256, GEMM_SMEM>>>(
        ctx, 1024, 0, owt, 1024, 0, out, 1024, 0, 1024, 1.0f, out_b);
}